// round 6
// baseline (speedup 1.0000x reference)
#include <cuda_runtime.h>

#define IMG   4096
#define TW    64                 // tile width  (x)
#define TH    64                 // tile height (y)
#define KY    16                 // y-outputs per thread
#define HALO  7
#define RW    (TW + 2*HALO)      // 78 raw columns
#define ROWS  (TH + 2*HALO)      // 78 smem rows
#define STRIDE 81                // odd -> conflict-free strided column access

__global__ __launch_bounds__(256, 5) void meanconv_hyb_kernel(
    const float* __restrict__ x,
    const float* __restrict__ mask,
    float* __restrict__ out)
{
    __shared__ float R[ROWS * STRIDE];   // 78*81*4 = 25.3 KB

    const int t   = threadIdx.x;
    const int gx0 = blockIdx.x * TW;
    const int gy0 = blockIdx.y * TH;

    // ---- Load clamped raw tile (replicate padding == index clamp) ----
    for (int idx = t; idx < ROWS * RW; idx += 256) {
        int r = idx / RW;
        int c = idx - r * RW;
        int gy = gy0 - HALO + r; gy = min(max(gy, 0), IMG - 1);
        int gx = gx0 - HALO + c; gx = min(max(gx, 0), IMG - 1);
        R[r * STRIDE + 1 + c] = x[gy * IMG + gx];
    }
    __syncthreads();

    // ---- Horizontal prefix, segmented halves (156 threads) ----
    if (t < 2 * ROWS) {
        const int row  = t >> 1;
        const int half = t & 1;
        float* rp = &R[row * STRIDE];
        if (half == 0) {
            rp[0] = 0.0f;
            float acc = 0.0f;
            #pragma unroll
            for (int c = 1; c <= 39; c++) { acc += rp[c]; rp[c] = acc; }
        } else {
            float acc = 0.0f;
            #pragma unroll
            for (int c = 40; c <= 78; c++) { acc += rp[c]; rp[c] = acc; }
        }
    }
    __syncthreads();

    // ---- Fix-up: add first-half total to second half ----
    if (t < 2 * ROWS) {
        const int row  = t >> 1;
        const int half = t & 1;
        float* rp = &R[row * STRIDE];
        const float tot = rp[39];
        const int c0 = half ? 59 : 40;
        const int c1 = half ? 78 : 58;
        for (int c = c0; c <= c1; c++) rp[c] += tot;
    }
    __syncthreads();

    // ---- Query: rings for p=1..4 (24 regs), smem re-read for p=5..7 ----
    const int tx = t & (TW - 1);
    const int y0 = (t >> 6) * KY;            // 0,16,32,48

    // rs_p(r) = Rb[r*STRIDE + p] - Rb[r*STRIDE - 1 - p], Rb centered at col tx+8
    const float* Rb = &R[tx + 8];

    #define RS(rr, pp) (Rb[(rr) * STRIDE + (pp)] - Rb[(rr) * STRIDE - 1 - (pp)])

    const float W1 = 1.0f/63.0f,  W2 = 1.0f/175.0f, W3 = 1.0f/343.0f,
                W4 = 1.0f/567.0f, W5 = 1.0f/847.0f, W6 = 1.0f/1183.0f,
                W7 = 1.0f/1575.0f;

    float ring[24];                       // p=1..4 rings, offsets 0,3,8,15
    const int ROFF[5] = {0, 0, 3, 8, 15};
    float B[7];

    // Init all 7 windows centered at output row y0 (smem row y0+7)
    #pragma unroll
    for (int p = 1; p <= 4; p++) {
        float b = 0.0f;
        #pragma unroll
        for (int i = 0; i <= 2 * p; i++) {
            const int r = y0 + HALO - p + i;
            float rs = RS(r, p);
            ring[ROFF[p] + i] = rs;
            b += rs;
        }
        B[p - 1] = b;
    }
    #pragma unroll
    for (int p = 5; p <= 7; p++) {
        float b = 0.0f;
        #pragma unroll
        for (int i = 0; i <= 2 * p; i++)
            b += RS(y0 + HALO - p + i, p);
        B[p - 1] = b;
    }

    {
        float acc =        W1 * B[0];
        acc = fmaf(W2, B[1], acc); acc = fmaf(W3, B[2], acc);
        acc = fmaf(W4, B[3], acc); acc = fmaf(W5, B[4], acc);
        acc = fmaf(W6, B[5], acc); acc = fmaf(W7, B[6], acc);
        const int g = (gy0 + y0) * IMG + gx0 + tx;
        out[g] = acc * mask[g];
    }

    // Steady state: fully unrolled; ring slots & all offsets static
    #pragma unroll
    for (int j = 1; j < KY; j++) {
        // small scales: ring buffers (2 LDS each)
        #pragma unroll
        for (int p = 1; p <= 4; p++) {
            const int r = y0 + j + HALO + p;
            float rs = RS(r, p);
            const int slot = ROFF[p] + (j - 1) % (2 * p + 1);  // compile-time
            B[p - 1] += rs - ring[slot];
            ring[slot] = rs;
        }
        // large scales: re-read expiring row (4 LDS each)
        #pragma unroll
        for (int p = 5; p <= 7; p++) {
            const int rn = y0 + j + HALO + p;
            const int ro = y0 + j + HALO - 1 - p;
            B[p - 1] += RS(rn, p) - RS(ro, p);
        }
        float acc =        W1 * B[0];
        acc = fmaf(W2, B[1], acc); acc = fmaf(W3, B[2], acc);
        acc = fmaf(W4, B[3], acc); acc = fmaf(W5, B[4], acc);
        acc = fmaf(W6, B[5], acc); acc = fmaf(W7, B[6], acc);
        const int g = (gy0 + y0 + j) * IMG + gx0 + tx;
        out[g] = acc * mask[g];
    }
    #undef RS
}

extern "C" void kernel_launch(void* const* d_in, const int* in_sizes, int n_in,
                              void* d_out, int out_size)
{
    (void)n_in; (void)in_sizes; (void)out_size;
    const float* x    = (const float*)d_in[0];
    const float* mask = (const float*)d_in[1];
    float* out        = (float*)d_out;

    dim3 grid(IMG / TW, IMG / TH);   // 64 x 64 tiles
    meanconv_hyb_kernel<<<grid, 256>>>(x, mask, out);
}